// round 3
// baseline (speedup 1.0000x reference)
#include <cuda_runtime.h>
#include <cuda_bf16.h>
#include <math.h>

#define N_NODES 8192
#define EMBED   64
#define HID0    256
#define HID1    256
#define HID2    128
#define ACTION  8192
#define IN_SIZE (N_NODES + EMBED)   // 8256
#define RPB 8                       // rows per block in matvec

// ---- scratch (__device__ globals; no allocation allowed) ----
__device__ float g_x[N_NODES];     // diagonal of state
__device__ float g_s[N_NODES];     // s = adj @ x
__device__ float g_t[HID0];
__device__ float g_fc1p[HID0];     // fc1 partial (state part)
__device__ float g_y1[HID0];
__device__ float g_y2[HID1];
__device__ float g_y3[HID2];
__device__ float g_dummy;          // prefetch sink

// K1: extract diagonal
__global__ void k_diag(const float* __restrict__ state) {
    int i = blockIdx.x * blockDim.x + threadIdx.x;
    if (i < N_NODES) g_x[i] = state[(size_t)i * (N_NODES + 1)];
}

// K2: blocks [0,1024): s[i] = dot(state[i,:], x) - x[i]^2   (the 256 MB pass)
//     blocks [1024,1280): fc1 partial: g_fc1p[r] = fc1_w[r,0:8192] . state[start,:]
__global__ void __launch_bounds__(256) k_matvec_fc1p(const float* __restrict__ state,
                                                     const int* __restrict__ start_p,
                                                     const float* __restrict__ fc1_w) {
    if (blockIdx.x < N_NODES / RPB) {
        int r0 = blockIdx.x * RPB;
        const float4* __restrict__ base = (const float4*)(state + (size_t)r0 * N_NODES);
        const float4* __restrict__ xp = (const float4*)g_x;
        float acc[RPB];
        #pragma unroll
        for (int r = 0; r < RPB; r++) acc[r] = 0.0f;

        for (int j = threadIdx.x; j < N_NODES / 4; j += 256) {
            float4 xv = xp[j];
            #pragma unroll
            for (int r = 0; r < RPB; r++) {
                float4 a = base[(size_t)r * (N_NODES / 4) + j];
                acc[r] += a.x * xv.x + a.y * xv.y + a.z * xv.z + a.w * xv.w;
            }
        }
        int lane = threadIdx.x & 31, wid = threadIdx.x >> 5;
        #pragma unroll
        for (int r = 0; r < RPB; r++)
            #pragma unroll
            for (int o = 16; o; o >>= 1) acc[r] += __shfl_down_sync(0xffffffffu, acc[r], o);
        __shared__ float sh[RPB][8];
        if (lane == 0) {
            #pragma unroll
            for (int r = 0; r < RPB; r++) sh[r][wid] = acc[r];
        }
        __syncthreads();
        if (threadIdx.x < RPB * 8) {
            int r = threadIdx.x >> 3, w = threadIdx.x & 7;
            float v = sh[r][w];
            v += __shfl_down_sync(0xffffffffu, v, 4, 8);
            v += __shfl_down_sync(0xffffffffu, v, 2, 8);
            v += __shfl_down_sync(0xffffffffu, v, 1, 8);
            if (w == 0) {
                int row = r0 + r;
                float xi = g_x[row];
                g_s[row] = v - xi * xi;
            }
        }
    } else {
        // fc1 partial: one block per output row r
        int r = blockIdx.x - N_NODES / RPB;
        int st = *start_p;
        const float4* __restrict__ w4 = (const float4*)(fc1_w + (size_t)r * IN_SIZE);
        const float4* __restrict__ s4 = (const float4*)(state + (size_t)st * N_NODES);
        float acc = 0.0f;
        #pragma unroll 8
        for (int j = threadIdx.x; j < N_NODES / 4; j += 256) {
            float4 a = w4[j];
            float4 b = s4[j];
            acc += a.x * b.x + a.y * b.y + a.z * b.z + a.w * b.w;
        }
        int lane = threadIdx.x & 31, wid = threadIdx.x >> 5;
        #pragma unroll
        for (int o = 16; o; o >>= 1) acc += __shfl_down_sync(0xffffffffu, acc, o);
        __shared__ float sh2[8];
        if (lane == 0) sh2[wid] = acc;
        __syncthreads();
        if (threadIdx.x < 8) {
            float v = sh2[threadIdx.x];
            v += __shfl_down_sync(0xffu, v, 4, 8);
            v += __shfl_down_sync(0xffu, v, 2, 8);
            v += __shfl_down_sync(0xffu, v, 1, 8);
            if (threadIdx.x == 0) g_fc1p[r] = v;
        }
    }
}

// K3: blocks [0,64): t[j0..j0+3] = sum_i adj[start,i] * relu(s[i]*w + b)
//     blocks [64,128): prefetch downstream weights into L2
__global__ void __launch_bounds__(256) k_t_pf(const float* __restrict__ state,
                                              const int* __restrict__ start_p,
                                              const float* __restrict__ gc1_w,
                                              const float* __restrict__ gc1_b,
                                              const float* __restrict__ gc2_w,
                                              const float* __restrict__ fc1_w,
                                              const float* __restrict__ fc2_w,
                                              const float* __restrict__ fc3_w,
                                              const float* __restrict__ fc4_w) {
    if (blockIdx.x < 64) {
        int j0 = blockIdx.x * 4;
        int st = *start_p;
        float w0 = gc1_w[j0], w1 = gc1_w[j0 + 1], w2 = gc1_w[j0 + 2], w3 = gc1_w[j0 + 3];
        float b0 = gc1_b[j0], b1 = gc1_b[j0 + 1], b2 = gc1_b[j0 + 2], b3 = gc1_b[j0 + 3];
        const float* __restrict__ row = state + (size_t)st * N_NODES;
        float a0 = 0.f, a1 = 0.f, a2 = 0.f, a3 = 0.f;
        for (int i = threadIdx.x; i < N_NODES; i += 256) {
            float a = (i == st) ? 0.0f : row[i];
            float s = g_s[i];
            a0 += a * fmaxf(fmaf(s, w0, b0), 0.0f);
            a1 += a * fmaxf(fmaf(s, w1, b1), 0.0f);
            a2 += a * fmaxf(fmaf(s, w2, b2), 0.0f);
            a3 += a * fmaxf(fmaf(s, w3, b3), 0.0f);
        }
        float acc[4] = {a0, a1, a2, a3};
        int lane = threadIdx.x & 31, wid = threadIdx.x >> 5;
        #pragma unroll
        for (int r = 0; r < 4; r++)
            #pragma unroll
            for (int o = 16; o; o >>= 1) acc[r] += __shfl_down_sync(0xffffffffu, acc[r], o);
        __shared__ float sh[4][8];
        if (lane == 0) {
            #pragma unroll
            for (int r = 0; r < 4; r++) sh[r][wid] = acc[r];
        }
        __syncthreads();
        if (threadIdx.x < 32) {
            int r = threadIdx.x >> 3, w = threadIdx.x & 7;
            float v = sh[r][w];
            v += __shfl_down_sync(0xffffffffu, v, 4, 8);
            v += __shfl_down_sync(0xffffffffu, v, 2, 8);
            v += __shfl_down_sync(0xffffffffu, v, 1, 8);
            if (w == 0) g_t[j0 + r] = v;
        }
    } else {
        // Prefetch: pull downstream weights into L2 while k_t runs.
        int tid = (blockIdx.x - 64) * 256 + threadIdx.x;
        const int stride = 64 * 256;
        float acc = 0.0f;
        const float4* w;
        w = (const float4*)gc2_w;   // 4096 f4
        for (int i = tid; i < HID0 * EMBED / 4; i += stride) { float4 v = w[i]; acc += v.x + v.y + v.z + v.w; }
        w = (const float4*)fc2_w;   // 16384 f4
        for (int i = tid; i < HID1 * HID0 / 4; i += stride) { float4 v = w[i]; acc += v.x + v.y + v.z + v.w; }
        w = (const float4*)fc3_w;   // 8192 f4
        for (int i = tid; i < HID2 * HID1 / 4; i += stride) { float4 v = w[i]; acc += v.x + v.y + v.z + v.w; }
        w = (const float4*)fc4_w;   // 262144 f4
        for (int i = tid; i < ACTION * HID2 / 4; i += stride) { float4 v = w[i]; acc += v.x + v.y + v.z + v.w; }
        // fc1_w embedding tails: row r, float4 index r*2064 + 2048 + c, c in [0,16)
        w = (const float4*)fc1_w;
        for (int i = tid; i < HID0 * 16; i += stride) {
            int r = i >> 4, c = i & 15;
            float4 v = w[(size_t)r * (IN_SIZE / 4) + (N_NODES / 4) + c];
            acc += v.x + v.y + v.z + v.w;
        }
        if (acc == 1.2345e30f) g_dummy = acc;  // never true; keeps loads live
    }
}

// K4 (one block, 256 threads): emb = log_softmax(relu(t@gc2_w+b)); then
// y1[r] = relu(g_fc1p[r] + fc1_w[r,8192:8256].emb + fc1_b[r])
__global__ void __launch_bounds__(256) k_emb_fc1(const float* __restrict__ gc2_w,
                                                 const float* __restrict__ gc2_b,
                                                 const float* __restrict__ fc1_w,
                                                 const float* __restrict__ fc1_b) {
    __shared__ float part[4][EMBED];
    __shared__ float hv[EMBED];
    __shared__ float emb[EMBED];
    __shared__ float red[1];
    int c = threadIdx.x & 63;
    int p = threadIdx.x >> 6;
    float u = 0.0f;
    #pragma unroll 8
    for (int j = p * 64; j < p * 64 + 64; j++)
        u = fmaf(g_t[j], gc2_w[j * EMBED + c], u);
    part[p][c] = u;
    __syncthreads();
    if (threadIdx.x < EMBED) {
        float h = part[0][c] + part[1][c] + part[2][c] + part[3][c] + gc2_b[c];
        hv[c] = fmaxf(h, 0.0f);
    }
    __syncthreads();
    if (threadIdx.x < 32) {
        float m = fmaxf(hv[threadIdx.x], hv[threadIdx.x + 32]);
        #pragma unroll
        for (int o = 16; o; o >>= 1) m = fmaxf(m, __shfl_xor_sync(0xffffffffu, m, o));
        float s = expf(hv[threadIdx.x] - m) + expf(hv[threadIdx.x + 32] - m);
        #pragma unroll
        for (int o = 16; o; o >>= 1) s += __shfl_xor_sync(0xffffffffu, s, o);
        if (threadIdx.x == 0) red[0] = m + logf(s);
    }
    __syncthreads();
    if (threadIdx.x < EMBED) emb[c] = hv[c] - red[0];
    __syncthreads();
    // fc1 finish: thread r handles output r
    {
        int r = threadIdx.x;
        const float* __restrict__ tail = fc1_w + (size_t)r * IN_SIZE + N_NODES;
        float acc = g_fc1p[r];
        #pragma unroll 16
        for (int k = 0; k < EMBED; k++) acc = fmaf(tail[k], emb[k], acc);
        g_y1[r] = fmaxf(acc + fc1_b[r], 0.0f);
    }
}

// K5: fc2, warp per output. 32 blocks x 8 warps = 256 outputs.
__global__ void __launch_bounds__(256) k_fc2(const float* __restrict__ fc2_w,
                                             const float* __restrict__ fc2_b) {
    int warp = threadIdx.x >> 5, lane = threadIdx.x & 31;
    int o = blockIdx.x * 8 + warp;
    const float4* __restrict__ w4 = (const float4*)(fc2_w + (size_t)o * HID0);
    const float4* __restrict__ y4 = (const float4*)g_y1;
    float acc = 0.0f;
    #pragma unroll
    for (int k = lane; k < HID0 / 4; k += 32) {
        float4 w = w4[k];
        float4 y = y4[k];
        acc += w.x * y.x + w.y * y.y + w.z * y.z + w.w * y.w;
    }
    #pragma unroll
    for (int off = 16; off; off >>= 1) acc += __shfl_down_sync(0xffffffffu, acc, off);
    if (lane == 0) g_y2[o] = fmaxf(acc + fc2_b[o], 0.0f);
}

// K6: fc3, warp per output. 16 blocks x 8 warps = 128 outputs.
__global__ void __launch_bounds__(256) k_fc3(const float* __restrict__ fc3_w,
                                             const float* __restrict__ fc3_b) {
    int warp = threadIdx.x >> 5, lane = threadIdx.x & 31;
    int o = blockIdx.x * 8 + warp;
    const float4* __restrict__ w4 = (const float4*)(fc3_w + (size_t)o * HID1);
    const float4* __restrict__ y4 = (const float4*)g_y2;
    float acc = 0.0f;
    #pragma unroll
    for (int k = lane; k < HID1 / 4; k += 32) {
        float4 w = w4[k];
        float4 y = y4[k];
        acc += w.x * y.x + w.y * y.y + w.z * y.z + w.w * y.w;
    }
    #pragma unroll
    for (int off = 16; off; off >>= 1) acc += __shfl_down_sync(0xffffffffu, acc, off);
    if (lane == 0) g_y3[o] = fmaxf(acc + fc3_b[o], 0.0f);
}

// K7: out[a] = relu(fc4_w[a,:] . y3 + fc4_b[a]); one warp per output
__global__ void __launch_bounds__(256) k_fc4(const float* __restrict__ fc4_w,
                                             const float* __restrict__ fc4_b,
                                             float* __restrict__ out) {
    __shared__ float y3s[HID2];
    int tid = threadIdx.x;
    if (tid < HID2) y3s[tid] = g_y3[tid];
    __syncthreads();
    int warp = tid >> 5, lane = tid & 31;
    int a = blockIdx.x * 8 + warp;
    const float4* __restrict__ w4 = (const float4*)(fc4_w + (size_t)a * HID2);
    float4 w = w4[lane];
    float acc = w.x * y3s[lane * 4 + 0] + w.y * y3s[lane * 4 + 1] +
                w.z * y3s[lane * 4 + 2] + w.w * y3s[lane * 4 + 3];
    #pragma unroll
    for (int o = 16; o; o >>= 1) acc += __shfl_down_sync(0xffffffffu, acc, o);
    if (lane == 0) out[a] = fmaxf(acc + fc4_b[a], 0.0f);
}

extern "C" void kernel_launch(void* const* d_in, const int* in_sizes, int n_in,
                              void* d_out, int out_size) {
    const float* state = (const float*)d_in[0];
    const int*   start = (const int*)d_in[1];
    const float* gc1_w = (const float*)d_in[2];
    const float* gc1_b = (const float*)d_in[3];
    const float* gc2_w = (const float*)d_in[4];
    const float* gc2_b = (const float*)d_in[5];
    const float* fc1_w = (const float*)d_in[6];
    const float* fc1_b = (const float*)d_in[7];
    const float* fc2_w = (const float*)d_in[8];
    const float* fc2_b = (const float*)d_in[9];
    const float* fc3_w = (const float*)d_in[10];
    const float* fc3_b = (const float*)d_in[11];
    const float* fc4_w = (const float*)d_in[12];
    const float* fc4_b = (const float*)d_in[13];
    float* out = (float*)d_out;

    k_diag<<<N_NODES / 256, 256>>>(state);
    k_matvec_fc1p<<<N_NODES / RPB + HID0, 256>>>(state, start, fc1_w);
    k_t_pf<<<128, 256>>>(state, start, gc1_w, gc1_b, gc2_w, fc1_w, fc2_w, fc3_w, fc4_w);
    k_emb_fc1<<<1, 256>>>(gc2_w, gc2_b, fc1_w, fc1_b);
    k_fc2<<<HID1 / 8, 256>>>(fc2_w, fc2_b);
    k_fc3<<<HID2 / 8, 256>>>(fc3_w, fc3_b);
    k_fc4<<<ACTION / 8, 256>>>(fc4_w, fc4_b, out);
}

// round 4
// speedup vs baseline: 1.1061x; 1.1061x over previous
#include <cuda_runtime.h>
#include <cuda_bf16.h>
#include <math.h>

#define N_NODES 8192
#define EMBED   64
#define HID0    256
#define HID1    256
#define HID2    128
#define ACTION  8192
#define IN_SIZE (N_NODES + EMBED)   // 8256
#define ROW_F4  (IN_SIZE / 4)       // 2064
#define RPB 8                       // rows per block in matvec

// ---- scratch (__device__ globals; no allocation allowed) ----
__device__ float g_x[N_NODES];     // diagonal of state
__device__ float g_s[N_NODES];     // s = adj @ x
__device__ float g_t[HID0];
__device__ float g_fc1p[HID0];     // fc1 partial (state part)
__device__ float g_y3[HID2];
__device__ float g_dummy;          // prefetch sink

// K1: extract diagonal
__global__ void k_diag(const float* __restrict__ state) {
    int i = blockIdx.x * blockDim.x + threadIdx.x;
    if (i < N_NODES) g_x[i] = state[(size_t)i * (N_NODES + 1)];
}

// K2: blocks [0,1024): s[i] = dot(state[i,:], x) - x[i]^2   (the 256 MB pass)
//     blocks [1024,1280): fc1 partial: g_fc1p[r] = fc1_w[r,0:8192] . state[start,:]
__global__ void __launch_bounds__(256) k_matvec_fc1p(const float* __restrict__ state,
                                                     const int* __restrict__ start_p,
                                                     const float* __restrict__ fc1_w) {
    if (blockIdx.x < N_NODES / RPB) {
        int r0 = blockIdx.x * RPB;
        const float4* __restrict__ base = (const float4*)(state + (size_t)r0 * N_NODES);
        const float4* __restrict__ xp = (const float4*)g_x;
        float acc[RPB];
        #pragma unroll
        for (int r = 0; r < RPB; r++) acc[r] = 0.0f;

        for (int j = threadIdx.x; j < N_NODES / 4; j += 256) {
            float4 xv = xp[j];
            #pragma unroll
            for (int r = 0; r < RPB; r++) {
                float4 a = base[(size_t)r * (N_NODES / 4) + j];
                acc[r] += a.x * xv.x + a.y * xv.y + a.z * xv.z + a.w * xv.w;
            }
        }
        int lane = threadIdx.x & 31, wid = threadIdx.x >> 5;
        #pragma unroll
        for (int r = 0; r < RPB; r++)
            #pragma unroll
            for (int o = 16; o; o >>= 1) acc[r] += __shfl_down_sync(0xffffffffu, acc[r], o);
        __shared__ float sh[RPB][8];
        if (lane == 0) {
            #pragma unroll
            for (int r = 0; r < RPB; r++) sh[r][wid] = acc[r];
        }
        __syncthreads();
        if (threadIdx.x < RPB * 8) {
            int r = threadIdx.x >> 3, w = threadIdx.x & 7;
            float v = sh[r][w];
            v += __shfl_down_sync(0xffffffffu, v, 4, 8);
            v += __shfl_down_sync(0xffffffffu, v, 2, 8);
            v += __shfl_down_sync(0xffffffffu, v, 1, 8);
            if (w == 0) {
                int row = r0 + r;
                float xi = g_x[row];
                g_s[row] = v - xi * xi;
            }
        }
    } else {
        // fc1 partial: one block per output row r
        int r = blockIdx.x - N_NODES / RPB;
        int st = *start_p;
        const float4* __restrict__ w4 = (const float4*)(fc1_w + (size_t)r * IN_SIZE);
        const float4* __restrict__ s4 = (const float4*)(state + (size_t)st * N_NODES);
        float acc = 0.0f;
        #pragma unroll 8
        for (int j = threadIdx.x; j < N_NODES / 4; j += 256) {
            float4 a = w4[j];
            float4 b = s4[j];
            acc += a.x * b.x + a.y * b.y + a.z * b.z + a.w * b.w;
        }
        int lane = threadIdx.x & 31, wid = threadIdx.x >> 5;
        #pragma unroll
        for (int o = 16; o; o >>= 1) acc += __shfl_down_sync(0xffffffffu, acc, o);
        __shared__ float sh2[8];
        if (lane == 0) sh2[wid] = acc;
        __syncthreads();
        if (threadIdx.x < 8) {
            float v = sh2[threadIdx.x];
            v += __shfl_down_sync(0xffu, v, 4, 8);
            v += __shfl_down_sync(0xffu, v, 2, 8);
            v += __shfl_down_sync(0xffu, v, 1, 8);
            if (threadIdx.x == 0) g_fc1p[r] = v;
        }
    }
}

// K3: blocks [0,64): t[j0..j0+3] = sum_i adj[start,i] * relu(s[i]*w + b)
//     blocks [64,128): prefetch downstream weights into L2
__global__ void __launch_bounds__(256) k_t_pf(const float* __restrict__ state,
                                              const int* __restrict__ start_p,
                                              const float* __restrict__ gc1_w,
                                              const float* __restrict__ gc1_b,
                                              const float* __restrict__ gc2_w,
                                              const float* __restrict__ fc1_w,
                                              const float* __restrict__ fc2_w,
                                              const float* __restrict__ fc3_w,
                                              const float* __restrict__ fc4_w) {
    if (blockIdx.x < 64) {
        int j0 = blockIdx.x * 4;
        int st = *start_p;
        float w0 = gc1_w[j0], w1 = gc1_w[j0 + 1], w2 = gc1_w[j0 + 2], w3 = gc1_w[j0 + 3];
        float b0 = gc1_b[j0], b1 = gc1_b[j0 + 1], b2 = gc1_b[j0 + 2], b3 = gc1_b[j0 + 3];
        const float* __restrict__ row = state + (size_t)st * N_NODES;
        float a0 = 0.f, a1 = 0.f, a2 = 0.f, a3 = 0.f;
        for (int i = threadIdx.x; i < N_NODES; i += 256) {
            float a = (i == st) ? 0.0f : row[i];
            float s = g_s[i];
            a0 += a * fmaxf(fmaf(s, w0, b0), 0.0f);
            a1 += a * fmaxf(fmaf(s, w1, b1), 0.0f);
            a2 += a * fmaxf(fmaf(s, w2, b2), 0.0f);
            a3 += a * fmaxf(fmaf(s, w3, b3), 0.0f);
        }
        float acc[4] = {a0, a1, a2, a3};
        int lane = threadIdx.x & 31, wid = threadIdx.x >> 5;
        #pragma unroll
        for (int r = 0; r < 4; r++)
            #pragma unroll
            for (int o = 16; o; o >>= 1) acc[r] += __shfl_down_sync(0xffffffffu, acc[r], o);
        __shared__ float sh[4][8];
        if (lane == 0) {
            #pragma unroll
            for (int r = 0; r < 4; r++) sh[r][wid] = acc[r];
        }
        __syncthreads();
        if (threadIdx.x < 32) {
            int r = threadIdx.x >> 3, w = threadIdx.x & 7;
            float v = sh[r][w];
            v += __shfl_down_sync(0xffffffffu, v, 4, 8);
            v += __shfl_down_sync(0xffffffffu, v, 2, 8);
            v += __shfl_down_sync(0xffffffffu, v, 1, 8);
            if (w == 0) g_t[j0 + r] = v;
        }
    } else {
        // Prefetch downstream weights into L2 while k_t computes.
        int tid = (blockIdx.x - 64) * 256 + threadIdx.x;
        const int stride = 64 * 256;
        float acc = 0.0f;
        const float4* w;
        w = (const float4*)gc2_w;
        for (int i = tid; i < HID0 * EMBED / 4; i += stride) { float4 v = w[i]; acc += v.x + v.y + v.z + v.w; }
        w = (const float4*)fc2_w;
        for (int i = tid; i < HID1 * HID0 / 4; i += stride) { float4 v = w[i]; acc += v.x + v.y + v.z + v.w; }
        w = (const float4*)fc3_w;
        for (int i = tid; i < HID2 * HID1 / 4; i += stride) { float4 v = w[i]; acc += v.x + v.y + v.z + v.w; }
        w = (const float4*)fc4_w;
        for (int i = tid; i < ACTION * HID2 / 4; i += stride) { float4 v = w[i]; acc += v.x + v.y + v.z + v.w; }
        // fc1_w embedding tails: row r, float4 index r*2064 + 2048 + c, c in [0,16)
        w = (const float4*)fc1_w;
        for (int i = tid; i < HID0 * 16; i += stride) {
            int r = i >> 4, c = i & 15;
            float4 v = w[(size_t)r * ROW_F4 + (N_NODES / 4) + c];
            acc += v.x + v.y + v.z + v.w;
        }
        if (acc == 1.2345e30f) g_dummy = acc;  // never true; keeps loads live
    }
}

// K4 (one block, 1024 threads): emb -> fc1 finish -> fc2 -> fc3, all coalesced.
__global__ void __launch_bounds__(1024) k_tail(const float* __restrict__ gc2_w,
                                               const float* __restrict__ gc2_b,
                                               const float* __restrict__ fc1_w,
                                               const float* __restrict__ fc1_b,
                                               const float* __restrict__ fc2_w,
                                               const float* __restrict__ fc2_b,
                                               const float* __restrict__ fc3_w,
                                               const float* __restrict__ fc3_b) {
    __shared__ float ts[HID0];
    __shared__ float part[16][EMBED];
    __shared__ float hv[EMBED];
    __shared__ float emb[EMBED];
    __shared__ float y1s[HID0];
    __shared__ float y2s[HID1];
    __shared__ float red[1];
    int tid = threadIdx.x;

    // Stage A: u[c] = sum_j t[j] * gc2_w[j,c]   (1024 threads: c = tid&63, p = tid>>6)
    if (tid < HID0) ts[tid] = g_t[tid];
    __syncthreads();
    {
        int c = tid & 63;
        int p = tid >> 6;          // 0..15, 16 j's each
        float u = 0.0f;
        #pragma unroll
        for (int j = p * 16; j < p * 16 + 16; j++)
            u = fmaf(ts[j], gc2_w[j * EMBED + c], u);
        part[p][c] = u;
    }
    __syncthreads();
    if (tid < EMBED) {
        float h = 0.0f;
        #pragma unroll
        for (int p = 0; p < 16; p++) h += part[p][tid];
        hv[tid] = fmaxf(h + gc2_b[tid], 0.0f);
    }
    __syncthreads();
    if (tid < 32) {
        float m = fmaxf(hv[tid], hv[tid + 32]);
        #pragma unroll
        for (int o = 16; o; o >>= 1) m = fmaxf(m, __shfl_xor_sync(0xffffffffu, m, o));
        float s = expf(hv[tid] - m) + expf(hv[tid + 32] - m);
        #pragma unroll
        for (int o = 16; o; o >>= 1) s += __shfl_xor_sync(0xffffffffu, s, o);
        if (tid == 0) red[0] = m + logf(s);
    }
    __syncthreads();
    if (tid < EMBED) emb[tid] = hv[tid] - red[0];
    __syncthreads();

    // Stage B: y1[r] = relu(g_fc1p[r] + tail[r,:].emb + fc1_b[r])
    // 4 threads per row; each reads 4 consecutive float4 (coalesced 256B per row).
    {
        int r = tid >> 2, p = tid & 3;
        const float4* __restrict__ w4 = (const float4*)fc1_w;
        const float4* __restrict__ e4 = (const float4*)emb;
        float acc = 0.0f;
        #pragma unroll
        for (int i = 0; i < 4; i++) {
            float4 w = w4[(size_t)r * ROW_F4 + (N_NODES / 4) + p * 4 + i];
            float4 e = e4[p * 4 + i];
            acc += w.x * e.x + w.y * e.y + w.z * e.z + w.w * e.w;
        }
        acc += __shfl_down_sync(0xffffffffu, acc, 2, 4);
        acc += __shfl_down_sync(0xffffffffu, acc, 1, 4);
        if (p == 0) y1s[r] = fmaxf(acc + g_fc1p[r] + fc1_b[r], 0.0f);
    }
    __syncthreads();

    // Stage C: y2[o] = relu(fc2_w[o,:].y1 + b)  (4 threads per output, 64 f4/row)
    {
        int o = tid >> 2, p = tid & 3;
        const float4* __restrict__ w4 = (const float4*)(fc2_w + (size_t)o * HID0);
        const float4* __restrict__ y4 = (const float4*)y1s;
        float acc = 0.0f;
        #pragma unroll
        for (int i = 0; i < 16; i++) {
            float4 w = w4[i * 4 + p];
            float4 y = y4[i * 4 + p];
            acc += w.x * y.x + w.y * y.y + w.z * y.z + w.w * y.w;
        }
        acc += __shfl_down_sync(0xffffffffu, acc, 2, 4);
        acc += __shfl_down_sync(0xffffffffu, acc, 1, 4);
        if (p == 0) y2s[o] = fmaxf(acc + fc2_b[o], 0.0f);
    }
    __syncthreads();

    // Stage D: y3[o] = relu(fc3_w[o,:].y2 + b)  (8 threads per output, 64 f4/row)
    {
        int o = tid >> 3, p = tid & 7;
        const float4* __restrict__ w4 = (const float4*)(fc3_w + (size_t)o * HID1);
        const float4* __restrict__ y4 = (const float4*)y2s;
        float acc = 0.0f;
        #pragma unroll
        for (int i = 0; i < 8; i++) {
            float4 w = w4[i * 8 + p];
            float4 y = y4[i * 8 + p];
            acc += w.x * y.x + w.y * y.y + w.z * y.z + w.w * y.w;
        }
        acc += __shfl_down_sync(0xffffffffu, acc, 4, 8);
        acc += __shfl_down_sync(0xffffffffu, acc, 2, 8);
        acc += __shfl_down_sync(0xffffffffu, acc, 1, 8);
        if (p == 0 && o < HID2) g_y3[o] = fmaxf(acc + fc3_b[o], 0.0f);
    }
}

// K5: out[a] = relu(fc4_w[a,:] . y3 + fc4_b[a]); one warp per output
__global__ void __launch_bounds__(256) k_fc4(const float* __restrict__ fc4_w,
                                             const float* __restrict__ fc4_b,
                                             float* __restrict__ out) {
    __shared__ float y3s[HID2];
    int tid = threadIdx.x;
    if (tid < HID2) y3s[tid] = g_y3[tid];
    __syncthreads();
    int warp = tid >> 5, lane = tid & 31;
    int a = blockIdx.x * 8 + warp;
    const float4* __restrict__ w4 = (const float4*)(fc4_w + (size_t)a * HID2);
    float4 w = w4[lane];
    float acc = w.x * y3s[lane * 4 + 0] + w.y * y3s[lane * 4 + 1] +
                w.z * y3s[lane * 4 + 2] + w.w * y3s[lane * 4 + 3];
    #pragma unroll
    for (int o = 16; o; o >>= 1) acc += __shfl_down_sync(0xffffffffu, acc, o);
    if (lane == 0) out[a] = fmaxf(acc + fc4_b[a], 0.0f);
}

extern "C" void kernel_launch(void* const* d_in, const int* in_sizes, int n_in,
                              void* d_out, int out_size) {
    const float* state = (const float*)d_in[0];
    const int*   start = (const int*)d_in[1];
    const float* gc1_w = (const float*)d_in[2];
    const float* gc1_b = (const float*)d_in[3];
    const float* gc2_w = (const float*)d_in[4];
    const float* gc2_b = (const float*)d_in[5];
    const float* fc1_w = (const float*)d_in[6];
    const float* fc1_b = (const float*)d_in[7];
    const float* fc2_w = (const float*)d_in[8];
    const float* fc2_b = (const float*)d_in[9];
    const float* fc3_w = (const float*)d_in[10];
    const float* fc3_b = (const float*)d_in[11];
    const float* fc4_w = (const float*)d_in[12];
    const float* fc4_b = (const float*)d_in[13];
    float* out = (float*)d_out;

    k_diag<<<N_NODES / 256, 256>>>(state);
    k_matvec_fc1p<<<N_NODES / RPB + HID0, 256>>>(state, start, fc1_w);
    k_t_pf<<<128, 256>>>(state, start, gc1_w, gc1_b, gc2_w, fc1_w, fc2_w, fc3_w, fc4_w);
    k_tail<<<1, 1024>>>(gc2_w, gc2_b, fc1_w, fc1_b, fc2_w, fc2_b, fc3_w, fc3_b);
    k_fc4<<<ACTION / 8, 256>>>(fc4_w, fc4_b, out);
}